// round 8
// baseline (speedup 1.0000x reference)
#include <cuda_runtime.h>
#include <cuda_bf16.h>
#include <math.h>
#include <stdint.h>

#define BATCH       32
#define HEADS       16
#define HEADDIM     128
#define BLOCK_SIZE  16
#define MAX_BLOCKS  128
#define MAX_CTX     (MAX_BLOCKS * BLOCK_SIZE)   // 2048
#define SCALE       (0.08838834764831845f)      // 1/sqrt(128)

#define NSPLIT      8
#define CHUNK       (MAX_CTX / NSPLIT)          // 256 tokens per split
#define NWARPS      8
#define NTHREADS    (NWARPS * 32)               // 256
#define TPS         16                          // tokens per stage == one KV block
#define STAGE_BYTES (TPS * HEADDIM * 4 * 2)     // K+V = 16 KB

// Split-KV partial results: per (b, h, split)
__device__ float g_m[BATCH * HEADS * NSPLIT];
__device__ float g_s[BATCH * HEADS * NSPLIT];
__device__ float g_acc[BATCH * HEADS * NSPLIT * HEADDIM];
__device__ unsigned int g_cnt[BATCH * HEADS];   // zero-init; reset by last CTA

__device__ __forceinline__ uint32_t smem_u32(const void* p)
{
    return (uint32_t)__cvta_generic_to_shared(p);
}
__device__ __forceinline__ void mbar_init(uint32_t a, uint32_t cnt)
{
    asm volatile("mbarrier.init.shared.b64 [%0], %1;" :: "r"(a), "r"(cnt) : "memory");
}
__device__ __forceinline__ void mbar_expect_tx(uint32_t a, uint32_t bytes)
{
    asm volatile("mbarrier.arrive.expect_tx.shared.b64 _, [%0], %1;"
                 :: "r"(a), "r"(bytes) : "memory");
}
__device__ __forceinline__ void mbar_wait(uint32_t a, uint32_t phase)
{
    asm volatile(
        "{\n\t"
        ".reg .pred P;\n\t"
        "WAIT_%=:\n\t"
        "mbarrier.try_wait.parity.acquire.cta.shared::cta.b64 P, [%0], %1, 0x989680;\n\t"
        "@P bra DONE_%=;\n\t"
        "bra WAIT_%=;\n\t"
        "DONE_%=:\n\t"
        "}"
        :: "r"(a), "r"(phase) : "memory");
}
__device__ __forceinline__ void bulk_cp(uint32_t dst_smem, const void* gsrc,
                                        uint32_t bytes, uint32_t mbar)
{
    asm volatile(
        "cp.async.bulk.shared::cluster.global.mbarrier::complete_tx::bytes "
        "[%0], [%1], %2, [%3];"
        :: "r"(dst_smem), "l"(gsrc), "r"(bytes), "r"(mbar) : "memory");
}
__device__ __forceinline__ void fence_proxy_async_cta()
{
    asm volatile("fence.proxy.async.shared::cta;" ::: "memory");
}

__global__ __launch_bounds__(NTHREADS, 6)
void paged_attn_split_kernel(const float* __restrict__ query,
                             const float* __restrict__ key_cache,
                             const float* __restrict__ value_cache,
                             const int*   __restrict__ block_tables,
                             const int*   __restrict__ context_lens,
                             float*       __restrict__ out)
{
    const int h     = blockIdx.x;
    const int b     = blockIdx.y;
    const int split = blockIdx.z;
    const int tid   = threadIdx.x;
    const int lane  = tid & 31;
    const int warp  = tid >> 5;

    const int bh    = b * HEADS + h;
    const int ctx   = context_lens[b];
    const int start = split * CHUNK;
    const int p     = bh * NSPLIT + split;
    const bool active = (start < ctx);

    __shared__ float s_k[2][TPS][HEADDIM];            // 16 KB
    __shared__ float s_v[2][TPS][HEADDIM];            // 16 KB
    __shared__ float s_acc[NWARPS * HEADDIM];         // 4 KB
    __shared__ int   s_btab[CHUNK / BLOCK_SIZE];      // 16 entries
    __shared__ float s_wm[NWARPS], s_ws[NWARPS];
    __shared__ unsigned int s_ticket;
    __shared__ __align__(8) unsigned long long s_mbar[2];

    if (active) {
        const int end = min(start + CHUNK, ctx);
        const int nst = (end - start + TPS - 1) / TPS;   // #stages, 1..16

        if (tid < CHUNK / BLOCK_SIZE)
            s_btab[tid] = block_tables[b * MAX_BLOCKS + (start >> 4) + tid];
        if (tid == 0) {
            mbar_init(smem_u32(&s_mbar[0]), 1);
            mbar_init(smem_u32(&s_mbar[1]), 1);
            fence_proxy_async_cta();
        }
        __syncthreads();

        const float4 q4 =
            reinterpret_cast<const float4*>(query + (size_t)bh * HEADDIM)[lane];

        // Warp 0 issues one stage: 32 lanes x one 512B bulk copy (16 K + 16 V rows).
        auto issue_stage = [&](int st) {
            const int buf = st & 1;
            const uint32_t mb = smem_u32(&s_mbar[buf]);
            if (lane == 0) mbar_expect_tx(mb, STAGE_BYTES);
            __syncwarp();
            const int  tok = lane & 15;
            const int  blk = s_btab[st];                 // stage == one KV block
            const size_t o = (((size_t)blk * BLOCK_SIZE + tok) * HEADS + h) * HEADDIM;
            if (lane < 16)
                bulk_cp(smem_u32(&s_k[buf][tok][0]), key_cache + o,
                        HEADDIM * 4, mb);
            else
                bulk_cp(smem_u32(&s_v[buf][tok][0]), value_cache + o,
                        HEADDIM * 4, mb);
        };

        float m = -INFINITY, s = 0.0f;
        float4 acc = make_float4(0.f, 0.f, 0.f, 0.f);

        if (warp == 0) issue_stage(0);

        for (int st = 0; st < nst; st++) {
            // Issue next stage: its buffer was last read in st-1, released by the
            // __syncthreads at the end of that iteration.
            if (warp == 0 && st + 1 < nst) issue_stage(st + 1);

            mbar_wait(smem_u32(&s_mbar[st & 1]), (st >> 1) & 1);

            const int buf  = st & 1;
            const int t0   = start + st * TPS + warp * 2;
            const int t1   = t0 + 1;
            const int tok0 = warp * 2, tok1 = tok0 + 1;

            const float4 k0 = reinterpret_cast<const float4*>(s_k[buf][tok0])[lane];
            const float4 k1 = reinterpret_cast<const float4*>(s_k[buf][tok1])[lane];
            const float4 v0 = reinterpret_cast<const float4*>(s_v[buf][tok0])[lane];
            const float4 v1 = reinterpret_cast<const float4*>(s_v[buf][tok1])[lane];

            float d0 = k0.x * q4.x + k0.y * q4.y + k0.z * q4.z + k0.w * q4.w;
            float d1 = k1.x * q4.x + k1.y * q4.y + k1.z * q4.z + k1.w * q4.w;
            #pragma unroll
            for (int o2 = 16; o2; o2 >>= 1) {
                d0 += __shfl_xor_sync(0xFFFFFFFFu, d0, o2);
                d1 += __shfl_xor_sync(0xFFFFFFFFu, d1, o2);
            }
            // Out-of-range tokens (tail stage) -> -inf score; cached data is finite,
            // so p*garbage = 0*finite = 0.
            d0 = (t0 < end) ? d0 * SCALE : -INFINITY;
            d1 = (t1 < end) ? d1 * SCALE : -INFINITY;

            const float mnew = fmaxf(m, fmaxf(d0, d1));
            const float resc = __expf(m - mnew);        // first iter: exp(-inf)=0
            const float p0   = __expf(d0 - mnew);
            const float p1   = __expf(d1 - mnew);
            s = s * resc + p0 + p1;
            acc.x = acc.x * resc + p0 * v0.x + p1 * v1.x;
            acc.y = acc.y * resc + p0 * v0.y + p1 * v1.y;
            acc.z = acc.z * resc + p0 * v0.z + p1 * v1.z;
            acc.w = acc.w * resc + p0 * v0.w + p1 * v1.w;
            m = mnew;

            __syncthreads();           // all reads done before buffer reuse
        }

        // ---- Merge warp partials -> split partial ----
        if (lane == 0) { s_wm[warp] = m; s_ws[warp] = s; }
        reinterpret_cast<float4*>(&s_acc[warp * HEADDIM])[lane] = acc;
        __syncthreads();

        if (tid < HEADDIM) {
            float gm = -INFINITY;
            #pragma unroll
            for (int w = 0; w < NWARPS; w++) gm = fmaxf(gm, s_wm[w]);
            float S = 0.0f, A = 0.0f;
            #pragma unroll
            for (int w = 0; w < NWARPS; w++) {
                const float wt = __expf(s_wm[w] - gm);
                S += wt * s_ws[w];
                A += wt * s_acc[w * HEADDIM + tid];
            }
            g_acc[(size_t)p * HEADDIM + tid] = A;
            if (tid == 0) { g_m[p] = gm; g_s[p] = S; }
        }
    } else {
        // Inactive split: neutral partial (merger skips g_acc when weight==0)
        if (tid == 0) { g_m[p] = -INFINITY; g_s[p] = 0.0f; }
    }

    // ---- Arrival ticket: last CTA of this (b,h) merges all splits ----
    if (tid < HEADDIM) __threadfence();   // order partial writes (writers only)
    __syncthreads();
    if (tid == 0) s_ticket = atomicAdd(&g_cnt[bh], 1u);
    __syncthreads();

    if (s_ticket == NSPLIT - 1) {
        __threadfence();    // acquire peers' partials
        if (tid < HEADDIM) {
            float m2[NSPLIT];
            float gm = -INFINITY;
            #pragma unroll
            for (int i = 0; i < NSPLIT; i++) {
                m2[i] = g_m[bh * NSPLIT + i];
                gm = fmaxf(gm, m2[i]);
            }
            float S = 0.0f, A = 0.0f;
            #pragma unroll
            for (int i = 0; i < NSPLIT; i++) {
                const float wt = __expf(m2[i] - gm);
                if (wt != 0.0f) {
                    S += wt * g_s[bh * NSPLIT + i];
                    A += wt * g_acc[((size_t)bh * NSPLIT + i) * HEADDIM + tid];
                }
            }
            out[(size_t)bh * HEADDIM + tid] = A / S;
        }
        if (tid == 0) g_cnt[bh] = 0u;   // reset for next graph replay
    }
}

extern "C" void kernel_launch(void* const* d_in, const int* in_sizes, int n_in,
                              void* d_out, int out_size)
{
    const float* query        = (const float*)d_in[0];
    const float* key_cache    = (const float*)d_in[1];
    const float* value_cache  = (const float*)d_in[2];
    const int*   block_tables = (const int*)d_in[3];
    const int*   context_lens = (const int*)d_in[4];
    float*       out          = (float*)d_out;

    dim3 grid(HEADS, BATCH, NSPLIT);
    paged_attn_split_kernel<<<grid, NTHREADS>>>(query, key_cache, value_cache,
                                                block_tables, context_lens, out);
}

// round 10
// speedup vs baseline: 1.1516x; 1.1516x over previous
#include <cuda_runtime.h>
#include <cuda_bf16.h>
#include <math.h>

#define BATCH       32
#define HEADS       16
#define HEADDIM     128
#define BLOCK_SIZE  16
#define MAX_BLOCKS  128
#define MAX_CTX     (MAX_BLOCKS * BLOCK_SIZE)   // 2048
#define SCALE       (0.08838834764831845f)      // 1/sqrt(128)
#define NEG_BIG     (-1e30f)                    // finite -inf stand-in (no NaN arith)

#define NSPLIT      16
#define CHUNK       (MAX_CTX / NSPLIT)          // 128 tokens per split
#define NWARPS      8
#define NTHREADS    (NWARPS * 32)               // 256
#define TPS         16                          // tokens per pipeline stage
#define NSTAGE      2                           // double buffer

// Split-KV partial results: per (b, h, split)
__device__ float g_m[BATCH * HEADS * NSPLIT];
__device__ float g_s[BATCH * HEADS * NSPLIT];
__device__ float g_acc[BATCH * HEADS * NSPLIT * HEADDIM];
__device__ unsigned int g_cnt[BATCH * HEADS];   // zero-init; reset by last CTA

__device__ __forceinline__ void cp_async16(void* smem_dst, const void* gmem_src)
{
    unsigned int s = (unsigned int)__cvta_generic_to_shared(smem_dst);
    asm volatile("cp.async.cg.shared.global [%0], [%1], 16;\n" :: "r"(s), "l"(gmem_src));
}
__device__ __forceinline__ void cp_commit()
{
    asm volatile("cp.async.commit_group;\n");
}
template <int N>
__device__ __forceinline__ void cp_wait()
{
    asm volatile("cp.async.wait_group %0;\n" :: "n"(N));
}

__global__ __launch_bounds__(NTHREADS, 6)
void paged_attn_split_kernel(const float* __restrict__ query,
                             const float* __restrict__ key_cache,
                             const float* __restrict__ value_cache,
                             const int*   __restrict__ block_tables,
                             const int*   __restrict__ context_lens,
                             float*       __restrict__ out)
{
    const int h     = blockIdx.x;
    const int b     = blockIdx.y;
    const int split = blockIdx.z;
    const int tid   = threadIdx.x;
    const int lane  = tid & 31;
    const int warp  = tid >> 5;

    const int bh    = b * HEADS + h;
    const int ctx   = context_lens[b];
    const int start = split * CHUNK;
    const int p     = bh * NSPLIT + split;
    const bool active = (start < ctx);

    __shared__ float s_k[NSTAGE][TPS][HEADDIM];       // 16 KB
    __shared__ float s_v[NSTAGE][TPS][HEADDIM];       // 16 KB
    __shared__ float s_acc[NWARPS * HEADDIM];         // 4 KB
    __shared__ int   s_btab[CHUNK / BLOCK_SIZE];      // 8 entries
    __shared__ float s_wm[NWARPS], s_ws[NWARPS];
    __shared__ unsigned int s_ticket;

    if (active) {
        const int end = min(start + CHUNK, ctx);
        const int nst = (end - start + TPS - 1) / TPS;   // #stages (1..8)

        if (tid < CHUNK / BLOCK_SIZE)
            s_btab[tid] = block_tables[b * MAX_BLOCKS + (start >> 4) + tid];
        __syncthreads();

        const float4 q4 =
            reinterpret_cast<const float4*>(query + (size_t)bh * HEADDIM)[lane];

        // ---- Stage fill: 512 slots of 16B per array; 2 K + 2 V cp.async per thread ----
        auto issue_stage = [&](int st) {
            const int buf  = st & 1;
            const int base = start + st * TPS;
            #pragma unroll
            for (int i = 0; i < 2; i++) {
                const int j    = tid + i * NTHREADS;   // 0..511
                const int tok  = j >> 5;
                const int part = j & 31;               // 16B unit within 512B row
                const int tg   = base + tok;
                if (tg < end) {
                    const int blk  = s_btab[(tg - start) >> 4];
                    const size_t o = (((size_t)blk * BLOCK_SIZE + (tg & 15)) * HEADS + h)
                                     * HEADDIM + part * 4;
                    cp_async16(&s_k[buf][tok][part * 4], key_cache + o);
                    cp_async16(&s_v[buf][tok][part * 4], value_cache + o);
                } else {
                    // zero V so 0-weight never multiplies garbage; K masked via score
                    *reinterpret_cast<float4*>(&s_v[buf][tok][part * 4]) =
                        make_float4(0.f, 0.f, 0.f, 0.f);
                }
            }
        };

        float m = NEG_BIG, s = 0.0f;
        float4 acc = make_float4(0.f, 0.f, 0.f, 0.f);

        issue_stage(0);
        cp_commit();

        for (int st = 0; st < nst; st++) {
            if (st + 1 < nst) {
                issue_stage(st + 1);
                cp_commit();
                cp_wait<1>();          // stage st complete, st+1 may be pending
            } else {
                cp_wait<0>();
            }
            __syncthreads();

            const int buf  = st & 1;
            const int t0   = start + st * TPS + warp * 2;
            const int t1   = t0 + 1;
            const int tok0 = warp * 2, tok1 = tok0 + 1;

            const float4 k0 = reinterpret_cast<const float4*>(s_k[buf][tok0])[lane];
            const float4 k1 = reinterpret_cast<const float4*>(s_k[buf][tok1])[lane];
            const float4 v0 = reinterpret_cast<const float4*>(s_v[buf][tok0])[lane];
            const float4 v1 = reinterpret_cast<const float4*>(s_v[buf][tok1])[lane];

            float d0 = k0.x * q4.x + k0.y * q4.y + k0.z * q4.z + k0.w * q4.w;
            float d1 = k1.x * q4.x + k1.y * q4.y + k1.z * q4.z + k1.w * q4.w;
            #pragma unroll
            for (int o2 = 16; o2; o2 >>= 1) {
                d0 += __shfl_xor_sync(0xFFFFFFFFu, d0, o2);
                d1 += __shfl_xor_sync(0xFFFFFFFFu, d1, o2);
            }
            // Finite sentinel: select kills NaN from uninit tail smem; no inf-inf.
            d0 = (t0 < end) ? d0 * SCALE : NEG_BIG;
            d1 = (t1 < end) ? d1 * SCALE : NEG_BIG;

            const float mnew = fmaxf(m, fmaxf(d0, d1));
            // Fully-idle warp: mnew==NEG_BIG, resc=p=1, but V is zeroed and the
            // merge weight exp(NEG_BIG - gm) underflows to 0 -> contributes nothing.
            const float resc = __expf(m - mnew);
            const float p0   = __expf(d0 - mnew);
            const float p1   = __expf(d1 - mnew);
            s = s * resc + p0 + p1;
            acc.x = acc.x * resc + p0 * v0.x + p1 * v1.x;
            acc.y = acc.y * resc + p0 * v0.y + p1 * v1.y;
            acc.z = acc.z * resc + p0 * v0.z + p1 * v1.z;
            acc.w = acc.w * resc + p0 * v0.w + p1 * v1.w;
            m = mnew;

            __syncthreads();           // all reads done before buffer reuse
        }

        // ---- Merge warp partials -> split partial ----
        if (lane == 0) { s_wm[warp] = m; s_ws[warp] = s; }
        reinterpret_cast<float4*>(&s_acc[warp * HEADDIM])[lane] = acc;
        __syncthreads();

        if (tid < HEADDIM) {
            float gm = NEG_BIG;
            #pragma unroll
            for (int w = 0; w < NWARPS; w++) gm = fmaxf(gm, s_wm[w]);
            float S = 0.0f, A = 0.0f;
            #pragma unroll
            for (int w = 0; w < NWARPS; w++) {
                const float wt = __expf(s_wm[w] - gm);   // idle warp: underflow -> 0
                S += wt * s_ws[w];
                A += wt * s_acc[w * HEADDIM + tid];
            }
            g_acc[(size_t)p * HEADDIM + tid] = A;
            if (tid == 0) { g_m[p] = gm; g_s[p] = S; }
        }
    } else {
        // Inactive split: neutral partial (merge weight underflows to 0)
        if (tid == 0) { g_m[p] = NEG_BIG; g_s[p] = 0.0f; }
    }

    // ---- Arrival ticket: last CTA of this (b,h) merges all splits ----
    if (tid < HEADDIM) __threadfence();   // order partial writes (writers only)
    __syncthreads();
    if (tid == 0) s_ticket = atomicAdd(&g_cnt[bh], 1u);
    __syncthreads();

    if (s_ticket == NSPLIT - 1) {
        __threadfence();    // acquire peers' partials
        if (tid < HEADDIM) {
            float m2[NSPLIT];
            float gm = NEG_BIG;
            #pragma unroll
            for (int i = 0; i < NSPLIT; i++) {
                m2[i] = g_m[bh * NSPLIT + i];
                gm = fmaxf(gm, m2[i]);
            }
            float S = 0.0f, A = 0.0f;
            #pragma unroll
            for (int i = 0; i < NSPLIT; i++) {
                const float wt = __expf(m2[i] - gm);     // inactive: underflow -> 0
                if (wt != 0.0f) {
                    S += wt * g_s[bh * NSPLIT + i];
                    A += wt * g_acc[((size_t)bh * NSPLIT + i) * HEADDIM + tid];
                }
            }
            out[(size_t)bh * HEADDIM + tid] = A / S;
        }
        if (tid == 0) g_cnt[bh] = 0u;   // reset for next graph replay
    }
}

extern "C" void kernel_launch(void* const* d_in, const int* in_sizes, int n_in,
                              void* d_out, int out_size)
{
    const float* query        = (const float*)d_in[0];
    const float* key_cache    = (const float*)d_in[1];
    const float* value_cache  = (const float*)d_in[2];
    const int*   block_tables = (const int*)d_in[3];
    const int*   context_lens = (const int*)d_in[4];
    float*       out          = (float*)d_out;

    dim3 grid(HEADS, BATCH, NSPLIT);
    paged_attn_split_kernel<<<grid, NTHREADS>>>(query, key_cache, value_cache,
                                                block_tables, context_lens, out);
}

// round 11
// speedup vs baseline: 1.1761x; 1.0212x over previous
#include <cuda_runtime.h>
#include <cuda_bf16.h>
#include <math.h>

#define BATCH       32
#define HEADS       16
#define HEADDIM     128
#define BLOCK_SIZE  16
#define MAX_BLOCKS  128
#define MAX_CTX     (MAX_BLOCKS * BLOCK_SIZE)   // 2048
#define SCALE       (0.08838834764831845f)      // 1/sqrt(128)
#define NEG_BIG     (-1e30f)                    // finite -inf stand-in (no NaN arith)

#define NSPLIT      16
#define CHUNK       (MAX_CTX / NSPLIT)          // 128 tokens per split
#define NWARPS      8
#define NTHREADS    (NWARPS * 32)               // 256
#define TPS         16                          // tokens per stage == one KV block
#define NSTAGE      2                           // double buffer
#define BLOCK_ELEMS ((size_t)BLOCK_SIZE * HEADS * HEADDIM)   // floats per KV block

// Split-KV partial results: per (b, h, split)
__device__ float g_m[BATCH * HEADS * NSPLIT];
__device__ float g_s[BATCH * HEADS * NSPLIT];
__device__ float g_acc[BATCH * HEADS * NSPLIT * HEADDIM];
__device__ unsigned int g_cnt[BATCH * HEADS];   // zero-init; reset by last CTA

__device__ __forceinline__ void cp_async16(void* smem_dst, const void* gmem_src)
{
    unsigned int s = (unsigned int)__cvta_generic_to_shared(smem_dst);
    asm volatile("cp.async.cg.shared.global [%0], [%1], 16;\n" :: "r"(s), "l"(gmem_src));
}
__device__ __forceinline__ void cp_commit()
{
    asm volatile("cp.async.commit_group;\n");
}
template <int N>
__device__ __forceinline__ void cp_wait()
{
    asm volatile("cp.async.wait_group %0;\n" :: "n"(N));
}

__global__ __launch_bounds__(NTHREADS, 6)
void paged_attn_split_kernel(const float* __restrict__ query,
                             const float* __restrict__ key_cache,
                             const float* __restrict__ value_cache,
                             const int*   __restrict__ block_tables,
                             const int*   __restrict__ context_lens,
                             float*       __restrict__ out)
{
    const int h     = blockIdx.x;
    const int b     = blockIdx.y;
    const int split = blockIdx.z;
    const int tid   = threadIdx.x;
    const int lane  = tid & 31;
    const int warp  = tid >> 5;

    const int bh    = b * HEADS + h;
    const int ctx   = context_lens[b];
    const int start = split * CHUNK;
    const int p     = bh * NSPLIT + split;
    const bool active = (start < ctx);

    __shared__ float s_k[NSTAGE][TPS][HEADDIM];       // 16 KB
    __shared__ float s_v[NSTAGE][TPS][HEADDIM];       // 16 KB
    __shared__ float s_acc[NWARPS * HEADDIM];         // 4 KB
    __shared__ int   s_btab[CHUNK / BLOCK_SIZE];      // 8 entries
    __shared__ float s_wm[NWARPS], s_ws[NWARPS];
    __shared__ unsigned int s_ticket;

    if (active) {
        const int end = min(start + CHUNK, ctx);
        const int nst = (end - start + TPS - 1) / TPS;   // #stages (1..8)

        if (tid < CHUNK / BLOCK_SIZE)
            s_btab[tid] = block_tables[b * MAX_BLOCKS + (start >> 4) + tid];
        __syncthreads();

        const float4 q4 =
            reinterpret_cast<const float4*>(query + (size_t)bh * HEADDIM)[lane];

        // ---- Hoisted per-thread fill constants --------------------------------
        // Stage == one KV block: block index is uniform (s_btab[st]); each thread
        // covers two 16B slots (tokens tokA=warp, tokB=warp+8) at fixed offsets.
        const int    tokA  = tid >> 5;              // 0..7
        const int    tokB  = tokA + 8;              // 8..15
        const int    part4 = (tid & 31) * 4;        // float offset of 16B unit
        const size_t cA = ((size_t)tokA * HEADS + h) * HEADDIM + part4;
        const size_t cB = ((size_t)tokB * HEADS + h) * HEADDIM + part4;

        auto issue_stage = [&](int st) {
            const int    buf  = st & 1;
            const int    base = start + st * TPS;
            const size_t bb   = (size_t)s_btab[st] * BLOCK_ELEMS;  // uniform LDS
            if (base + tokA < end) {
                cp_async16(&s_k[buf][tokA][part4], key_cache   + bb + cA);
                cp_async16(&s_v[buf][tokA][part4], value_cache + bb + cA);
            } else {
                *reinterpret_cast<float4*>(&s_v[buf][tokA][part4]) =
                    make_float4(0.f, 0.f, 0.f, 0.f);
            }
            if (base + tokB < end) {
                cp_async16(&s_k[buf][tokB][part4], key_cache   + bb + cB);
                cp_async16(&s_v[buf][tokB][part4], value_cache + bb + cB);
            } else {
                *reinterpret_cast<float4*>(&s_v[buf][tokB][part4]) =
                    make_float4(0.f, 0.f, 0.f, 0.f);
            }
        };

        float m = NEG_BIG, s = 0.0f;
        float4 acc = make_float4(0.f, 0.f, 0.f, 0.f);

        issue_stage(0);
        cp_commit();

        for (int st = 0; st < nst; st++) {
            if (st + 1 < nst) {
                issue_stage(st + 1);
                cp_commit();
                cp_wait<1>();          // stage st complete, st+1 may be pending
            } else {
                cp_wait<0>();
            }
            __syncthreads();

            const int buf  = st & 1;
            const int t0   = start + st * TPS + warp * 2;
            const int t1   = t0 + 1;
            const int tok0 = warp * 2, tok1 = tok0 + 1;

            const float4 k0 = reinterpret_cast<const float4*>(s_k[buf][tok0])[lane];
            const float4 k1 = reinterpret_cast<const float4*>(s_k[buf][tok1])[lane];
            const float4 v0 = reinterpret_cast<const float4*>(s_v[buf][tok0])[lane];
            const float4 v1 = reinterpret_cast<const float4*>(s_v[buf][tok1])[lane];

            float d0 = k0.x * q4.x + k0.y * q4.y + k0.z * q4.z + k0.w * q4.w;
            float d1 = k1.x * q4.x + k1.y * q4.y + k1.z * q4.z + k1.w * q4.w;
            #pragma unroll
            for (int o2 = 16; o2; o2 >>= 1) {
                d0 += __shfl_xor_sync(0xFFFFFFFFu, d0, o2);
                d1 += __shfl_xor_sync(0xFFFFFFFFu, d1, o2);
            }
            // Finite sentinel: select kills NaN from uninit tail smem; no inf-inf.
            d0 = (t0 < end) ? d0 * SCALE : NEG_BIG;
            d1 = (t1 < end) ? d1 * SCALE : NEG_BIG;

            const float mnew = fmaxf(m, fmaxf(d0, d1));
            // Fully-idle warp: mnew==NEG_BIG, resc=p=1, but V is zeroed and the
            // merge weight exp(NEG_BIG - gm) underflows to 0 -> contributes nothing.
            const float resc = __expf(m - mnew);
            const float p0   = __expf(d0 - mnew);
            const float p1   = __expf(d1 - mnew);
            s = s * resc + p0 + p1;
            acc.x = acc.x * resc + p0 * v0.x + p1 * v1.x;
            acc.y = acc.y * resc + p0 * v0.y + p1 * v1.y;
            acc.z = acc.z * resc + p0 * v0.z + p1 * v1.z;
            acc.w = acc.w * resc + p0 * v0.w + p1 * v1.w;
            m = mnew;

            __syncthreads();           // all reads done before buffer reuse
        }

        // ---- Merge warp partials -> split partial ----
        if (lane == 0) { s_wm[warp] = m; s_ws[warp] = s; }
        reinterpret_cast<float4*>(&s_acc[warp * HEADDIM])[lane] = acc;
        __syncthreads();

        if (tid < HEADDIM) {
            float gm = NEG_BIG;
            #pragma unroll
            for (int w = 0; w < NWARPS; w++) gm = fmaxf(gm, s_wm[w]);
            float S = 0.0f, A = 0.0f;
            #pragma unroll
            for (int w = 0; w < NWARPS; w++) {
                const float wt = __expf(s_wm[w] - gm);   // idle warp: underflow -> 0
                S += wt * s_ws[w];
                A += wt * s_acc[w * HEADDIM + tid];
            }
            g_acc[(size_t)p * HEADDIM + tid] = A;
            if (tid == 0) { g_m[p] = gm; g_s[p] = S; }
        }
    } else {
        // Inactive split: neutral partial (merge weight underflows to 0)
        if (tid == 0) { g_m[p] = NEG_BIG; g_s[p] = 0.0f; }
    }

    // ---- Arrival ticket: last CTA of this (b,h) merges all splits ----
    if (tid < HEADDIM) __threadfence();   // order partial writes (writers only)
    __syncthreads();
    if (tid == 0) s_ticket = atomicAdd(&g_cnt[bh], 1u);
    __syncthreads();

    if (s_ticket == NSPLIT - 1) {
        __threadfence();    // acquire peers' partials
        if (tid < HEADDIM) {
            float m2[NSPLIT];
            float gm = NEG_BIG;
            #pragma unroll
            for (int i = 0; i < NSPLIT; i++) {
                m2[i] = g_m[bh * NSPLIT + i];
                gm = fmaxf(gm, m2[i]);
            }
            float S = 0.0f, A = 0.0f;
            #pragma unroll
            for (int i = 0; i < NSPLIT; i++) {
                const float wt = __expf(m2[i] - gm);     // inactive: underflow -> 0
                if (wt != 0.0f) {
                    S += wt * g_s[bh * NSPLIT + i];
                    A += wt * g_acc[((size_t)bh * NSPLIT + i) * HEADDIM + tid];
                }
            }
            out[(size_t)bh * HEADDIM + tid] = A / S;
        }
        if (tid == 0) g_cnt[bh] = 0u;   // reset for next graph replay
    }
}

extern "C" void kernel_launch(void* const* d_in, const int* in_sizes, int n_in,
                              void* d_out, int out_size)
{
    const float* query        = (const float*)d_in[0];
    const float* key_cache    = (const float*)d_in[1];
    const float* value_cache  = (const float*)d_in[2];
    const int*   block_tables = (const int*)d_in[3];
    const int*   context_lens = (const int*)d_in[4];
    float*       out          = (float*)d_out;

    dim3 grid(HEADS, BATCH, NSPLIT);
    paged_attn_split_kernel<<<grid, NTHREADS>>>(query, key_cache, value_cache,
                                                block_tables, context_lens, out);
}